// round 6
// baseline (speedup 1.0000x reference)
#include <cuda_runtime.h>
#include <math.h>

// Problem geometry (fixed): B=8, C=3, H=W=512, TILE=128, STRIDE=64
// Cells: 8x8 of 64x64 per image; tile (ty,tx), ty,tx in [0,7), covers cells
// {ty,ty+1}x{tx,tx+1}. counts(pixel) = (#covering ty)*(#covering tx) exactly.
#define BSZ   8
#define NCH   3
#define HH    512
#define WW    512
#define PLANE (HH*WW)          // 262144
#define NCELL 8
#define NTILE 7
#define NBLK  512              // = BSZ * 64 cells = BSZ * 64 slabs
#define INV_TILE_ELEMS (1.0f/49152.0f)   // 1/(C*128*128)

__device__ float g_cellsum[BSZ * NCELL * NCELL];
__device__ int   g_bar1;     // phase-A arrivals (zero-init; self-resetting)
__device__ int   g_bar2;     // exit arrivals    (zero-init; self-resetting)

__device__ __forceinline__ float tanh_approx(float x) {
    float y;
    asm("tanh.approx.f32 %0, %1;" : "=f"(y) : "f"(x));
    return y;
}

// ---------------------------------------------------------------------------
// ONE fused kernel, 512 blocks x 256 threads (all co-resident: ~40 regs ->
// 6 blocks/SM limit, 148 SMs >= 512 blocks).
// Phase A: block = (b, cy, cx) 64x64 cell sum of (sum_c img)*mask.
// Software grid barrier (atomic counter + spin; counters self-reset so every
// graph replay sees zeroed state -> deterministic).
// Phase B: block = (b, 8-row slab); barrier-free lane-wise lavg + stream:
//   out = m * (0.5*tanh(0.25*(g + lavg*m)) + 0.5)   [== sigmoid(..)*m]
// ---------------------------------------------------------------------------
__global__ void __launch_bounds__(256) fused_kernel(
    const float* __restrict__ img, const float* __restrict__ mask,
    const float* __restrict__ gmap, float* __restrict__ out)
{
    const int tid = threadIdx.x;
    const int bid = blockIdx.x;            // 0..511

    // ================= Phase A: cell sum =================
    {
        const int b  = bid >> 6;
        const int c  = bid & 63;
        const int cy = c >> 3, cx = c & 7;

        const float* mb = mask + (b * HH + cy * 64) * WW + cx * 64;
        const float* ib = img + ((b * NCH) * HH + cy * 64) * WW + cx * 64;

        float acc = 0.0f;
        #pragma unroll
        for (int k = 0; k < 4; k++) {
            int f   = tid + k * 256;       // 0..1023 float4 slots (64 rows x 16)
            int row = f >> 4;
            int col = (f & 15) << 2;
            int off = row * WW + col;
            float4 m  = *(const float4*)(mb + off);
            float4 i0 = *(const float4*)(ib + off);
            float4 i1 = *(const float4*)(ib + PLANE + off);
            float4 i2 = *(const float4*)(ib + 2 * PLANE + off);
            acc += (i0.x + i1.x + i2.x) * m.x
                 + (i0.y + i1.y + i2.y) * m.y
                 + (i0.z + i1.z + i2.z) * m.z
                 + (i0.w + i1.w + i2.w) * m.w;
        }

        #pragma unroll
        for (int o = 16; o > 0; o >>= 1)
            acc += __shfl_xor_sync(0xffffffffu, acc, o);

        __shared__ float swarp[8];
        if ((tid & 31) == 0) swarp[tid >> 5] = acc;
        __syncthreads();
        if (tid == 0) {
            float v = swarp[0];
            #pragma unroll
            for (int w = 1; w < 8; w++) v += swarp[w];
            g_cellsum[bid] = v;
            __threadfence();               // make cellsum visible before arrive
            atomicAdd(&g_bar1, 1);
        }
    }

    // ================= Grid barrier =================
    if (tid == 0) {
        while (atomicAdd(&g_bar1, 0) < NBLK) { }
    }
    __syncthreads();   // releases the block; g_cellsum first-touched below
                       // (L1 flushed at launch -> misses fill from L2, fresh)

    // ================= Phase B: heatmap stream =================
    {
        const int b    = bid >> 6;
        const int slab = bid & 63;                 // 8 rows each
        const int base = slab * 4096;              // pixel base in plane
        const int cy   = slab >> 3;                // 64-row cell row

        // lane l computes lavg for cx = l&7 (broadcast-friendly L1 hits)
        const int lane = tid & 31;
        const int cxl  = lane & 7;
        const int ty0 = max(cy - 1, 0),  ty1 = min(cy, NTILE - 1);
        const int tx0 = max(cxl - 1, 0), tx1 = min(cxl, NTILE - 1);
        const float* csb = g_cellsum + (b << 6);
        float s = 0.0f;
        for (int ty = ty0; ty <= ty1; ty++)
            for (int tx = tx0; tx <= tx1; tx++)
                s += __ldg(csb + ((ty    ) << 3) + tx) + __ldg(csb + ((ty    ) << 3) + tx + 1)
                   + __ldg(csb + ((ty + 1) << 3) + tx) + __ldg(csb + ((ty + 1) << 3) + tx + 1);
        const float cnt    = (float)((ty1 - ty0 + 1) * (tx1 - tx0 + 1)); // 1,2,4
        const float lavg_l = s * INV_TILE_ELEMS * (1.0f / cnt);          // exact

        #pragma unroll
        for (int k = 0; k < 4; k++) {
            int idx = base + (tid + k * 256) * 4;          // float4-aligned px
            float4 m4 = *(const float4*)(mask + b * PLANE + idx);
            float4 g4 = *(const float4*)(gmap + b * PLANE + idx);
            int   cx  = (idx & 511) >> 6;
            float la  = __shfl_sync(0xffffffffu, lavg_l, cx);
            float4 o4;
            o4.x = m4.x * (0.5f * tanh_approx(0.25f * (g4.x + la * m4.x)) + 0.5f);
            o4.y = m4.y * (0.5f * tanh_approx(0.25f * (g4.y + la * m4.y)) + 0.5f);
            o4.z = m4.z * (0.5f * tanh_approx(0.25f * (g4.z + la * m4.z)) + 0.5f);
            o4.w = m4.w * (0.5f * tanh_approx(0.25f * (g4.w + la * m4.w)) + 0.5f);
            *(float4*)(out + b * PLANE + idx) = o4;
        }
    }

    // ================= Counter self-reset =================
    // Last block to arrive resets both counters; every other block has already
    // passed the phase-A spin (required to reach this add), so no spinner can
    // observe the reset mid-wait. Next graph replay sees zeroed counters.
    if (tid == 0) {
        int t = atomicAdd(&g_bar2, 1);
        if (t == NBLK - 1) {
            atomicExch(&g_bar1, 0);
            atomicExch(&g_bar2, 0);
        }
    }
}

// ---------------------------------------------------------------------------
// Inputs (metadata order):
//  0 image (8,3,512,512) f32 | 1 valid_mask (8,1,512,512) f32
//  2 global_heatmap (8,1,512,512) f32 | 3 tile_mask_bank (unused)
//  4 tile_mask_counts (unused) | 5 row_idx (unused) | 6 col_idx (unused)
// ---------------------------------------------------------------------------
extern "C" void kernel_launch(void* const* d_in, const int* in_sizes, int n_in,
                              void* d_out, int out_size)
{
    const float* image = (const float*)d_in[0];
    const float* mask  = (const float*)d_in[1];
    const float* gmap  = (const float*)d_in[2];
    float*       out   = (float*)d_out;

    fused_kernel<<<NBLK, 256>>>(image, mask, gmap, out);
}

// round 8
// speedup vs baseline: 1.5673x; 1.5673x over previous
#include <cuda_runtime.h>
#include <cuda_device_runtime_api.h>
#include <math.h>

// Problem geometry (fixed): B=8, C=3, H=W=512, TILE=128, STRIDE=64
// Cells: 8x8 of 64x64 per image; tile (ty,tx), ty,tx in [0,7), covers cells
// {ty,ty+1}x{tx,tx+1}. counts(pixel) = (#covering ty)*(#covering tx) exactly.
#define BSZ   8
#define NCH   3
#define HH    512
#define WW    512
#define PLANE (HH*WW)          // 262144
#define NCELL 8
#define NTILE 7
#define INV_TILE_ELEMS (1.0f/49152.0f)   // 1/(C*128*128)

__device__ float g_cellsum[BSZ * NCELL * NCELL];

__device__ __forceinline__ float tanh_approx(float x) {
    float y;
    asm("tanh.approx.f32 %0, %1;" : "=f"(y) : "f"(x));
    return y;
}

// ---------------------------------------------------------------------------
// Kernel 1: per-(b, cy, cx) 64x64 cell sum of (img_c0+img_c1+img_c2)*mask.
// 512 blocks x 256 threads (single wave). Loads batched 8-deep for MLP.
// Triggers programmatic launch completion at entry so kernel 2's blocks can
// board SMs as this kernel's blocks drain.
// ---------------------------------------------------------------------------
__global__ void __launch_bounds__(256) cell_sum_kernel(
    const float* __restrict__ img, const float* __restrict__ mask)
{
    cudaTriggerProgrammaticLaunchCompletion();

    const int cx = blockIdx.x, cy = blockIdx.y, b = blockIdx.z;
    const int tid = threadIdx.x;

    const float* mb = mask + (b * HH + cy * 64) * WW + cx * 64;
    const float* ib = img + ((b * NCH) * HH + cy * 64) * WW + cx * 64;

    float acc = 0.0f;
    #pragma unroll
    for (int h = 0; h < 2; h++) {                 // 2 batches of 2 slots
        float4 m[2], i0[2], i1[2], i2[2];
        #pragma unroll
        for (int j = 0; j < 2; j++) {             // 8 independent LDG.128
            int f   = tid + (h * 2 + j) * 256;    // 0..1023 float4 slots
            int row = f >> 4;
            int col = (f & 15) << 2;
            int off = row * WW + col;
            m[j]  = *(const float4*)(mb + off);
            i0[j] = *(const float4*)(ib + off);
            i1[j] = *(const float4*)(ib + PLANE + off);
            i2[j] = *(const float4*)(ib + 2 * PLANE + off);
        }
        #pragma unroll
        for (int j = 0; j < 2; j++) {
            acc += (i0[j].x + i1[j].x + i2[j].x) * m[j].x
                 + (i0[j].y + i1[j].y + i2[j].y) * m[j].y
                 + (i0[j].z + i1[j].z + i2[j].z) * m[j].z
                 + (i0[j].w + i1[j].w + i2[j].w) * m[j].w;
        }
    }

    #pragma unroll
    for (int o = 16; o > 0; o >>= 1)
        acc += __shfl_xor_sync(0xffffffffu, acc, o);

    __shared__ float swarp[8];
    if ((tid & 31) == 0) swarp[tid >> 5] = acc;
    __syncthreads();
    if (tid == 0) {
        float v = swarp[0];
        #pragma unroll
        for (int w = 1; w < 8; w++) v += swarp[w];
        g_cellsum[(b * NCELL + cy) * NCELL + cx] = v;
    }
}

// ---------------------------------------------------------------------------
// Kernel 2 (PDL secondary): issue all mask/gmap float4 LDGs FIRST (they do
// not depend on kernel 1), then cudaGridDependencySynchronize() before
// touching g_cellsum. Barrier-free per-lane lavg + __shfl distribution.
// 512 blocks (single wave), IPT=4 -> 8-row slab per block.
// ---------------------------------------------------------------------------
#define FK_IPT 4
#define FK_TPB 256
#define FK_PX_PER_BLOCK (FK_TPB * FK_IPT * 4)   // 4096 px = 8 rows

__global__ void __launch_bounds__(FK_TPB) final_kernel(
    const float* __restrict__ mask, const float* __restrict__ gmap,
    float* __restrict__ out)
{
    const int tid  = threadIdx.x;
    const int b    = blockIdx.y;
    const int base = blockIdx.x * FK_PX_PER_BLOCK;
    const int cy   = blockIdx.x >> 3;              // 8 slabs per 64-row cell

    // ---- pre-work: issue independent main loads while kernel 1 finishes ----
    float4 m4[FK_IPT], g4[FK_IPT];
    int    idxv[FK_IPT];
    #pragma unroll
    for (int k = 0; k < FK_IPT; k++) {
        idxv[k] = base + (tid + k * FK_TPB) * 4;   // float4-aligned pixel
        m4[k] = *(const float4*)(mask + b * PLANE + idxv[k]);
        g4[k] = *(const float4*)(gmap + b * PLANE + idxv[k]);
    }

    // ---- wait for kernel 1 completion (g_cellsum final) ----
    cudaGridDependencySynchronize();

    // ---- per-lane lavg for cx = lane&7; no shared memory, no barriers ----
    const int lane = tid & 31;
    const int cxl  = lane & 7;
    const int ty0 = max(cy - 1, 0),  ty1 = min(cy, NTILE - 1);
    const int tx0 = max(cxl - 1, 0), tx1 = min(cxl, NTILE - 1);
    const float* csb = g_cellsum + (b << 6);
    float s = 0.0f;
    for (int ty = ty0; ty <= ty1; ty++)
        for (int tx = tx0; tx <= tx1; tx++)
            s += csb[((ty    ) << 3) + tx] + csb[((ty    ) << 3) + tx + 1]
               + csb[((ty + 1) << 3) + tx] + csb[((ty + 1) << 3) + tx + 1];
    const float cnt    = (float)((ty1 - ty0 + 1) * (tx1 - tx0 + 1)); // 1,2,4
    const float lavg_l = s * INV_TILE_ELEMS * (1.0f / cnt);          // exact

    // ---- main math + store ----
    #pragma unroll
    for (int k = 0; k < FK_IPT; k++) {
        int   cx = (idxv[k] & 511) >> 6;
        float la = __shfl_sync(0xffffffffu, lavg_l, cx);
        float4 o4;
        o4.x = m4[k].x * (0.5f * tanh_approx(0.25f * (g4[k].x + la * m4[k].x)) + 0.5f);
        o4.y = m4[k].y * (0.5f * tanh_approx(0.25f * (g4[k].y + la * m4[k].y)) + 0.5f);
        o4.z = m4[k].z * (0.5f * tanh_approx(0.25f * (g4[k].z + la * m4[k].z)) + 0.5f);
        o4.w = m4[k].w * (0.5f * tanh_approx(0.25f * (g4[k].w + la * m4[k].w)) + 0.5f);
        *(float4*)(out + b * PLANE + idxv[k]) = o4;
    }
}

// ---------------------------------------------------------------------------
// Inputs (metadata order):
//  0 image (8,3,512,512) f32 | 1 valid_mask (8,1,512,512) f32
//  2 global_heatmap (8,1,512,512) f32 | 3 tile_mask_bank (unused)
//  4 tile_mask_counts (unused) | 5 row_idx (unused) | 6 col_idx (unused)
// ---------------------------------------------------------------------------
extern "C" void kernel_launch(void* const* d_in, const int* in_sizes, int n_in,
                              void* d_out, int out_size)
{
    const float* image = (const float*)d_in[0];
    const float* mask  = (const float*)d_in[1];
    const float* gmap  = (const float*)d_in[2];
    float*       out   = (float*)d_out;

    cell_sum_kernel<<<dim3(NCELL, NCELL, BSZ), 256>>>(image, mask);

    // Secondary launch with programmatic stream serialization: its blocks may
    // board as cell_sum_kernel drains; ordering is enforced inside via
    // cudaGridDependencySynchronize().
    cudaLaunchConfig_t cfg = {};
    cfg.gridDim  = dim3(PLANE / FK_PX_PER_BLOCK, BSZ);   // (64, 8) = 512 blocks
    cfg.blockDim = dim3(FK_TPB, 1, 1);
    cfg.dynamicSmemBytes = 0;
    cfg.stream = 0;                                      // legacy default stream
    cudaLaunchAttribute attr[1];
    attr[0].id = cudaLaunchAttributeProgrammaticStreamSerialization;
    attr[0].val.programmaticStreamSerializationAllowed = 1;
    cfg.attrs = attr;
    cfg.numAttrs = 1;
    cudaLaunchKernelEx(&cfg, final_kernel, mask, gmap, out);
}